// round 5
// baseline (speedup 1.0000x reference)
#include <cuda_runtime.h>
#include <math.h>
#include <stdint.h>

#define NN 50000
#define NE 1600000
#define CH 128
#define FE 50
#define TS 132
#define NTAB 16384

__device__ float g_h[(size_t)NN * CH];
__device__ float g_agg[(size_t)NN * CH];
__device__ float g_table[(size_t)(NTAB + 1) * CH];

__device__ __forceinline__ float ssp(float x) {
    return fmaxf(x, 0.0f) + log1pf(__expf(-fabsf(x))) - 0.69314718055994530942f;
}
__device__ __forceinline__ void red_add_v4(float* addr, float4 v) {
    asm volatile("red.global.add.v4.f32 [%0], {%1,%2,%3,%4};"
                 :: "l"(addr), "f"(v.x), "f"(v.y), "f"(v.z), "f"(v.w) : "memory");
}
__device__ __forceinline__ void split_tf32(float x, uint32_t& hi, uint32_t& lo) {
    asm("cvt.rna.tf32.f32 %0, %1;" : "=r"(hi) : "f"(x));
    float r = x - __uint_as_float(hi);
    asm("cvt.rna.tf32.f32 %0, %1;" : "=r"(lo) : "f"(r));
}
#define MMA(c, a0, a1, a2, a3, b0, b1)                                        \
    asm volatile("mma.sync.aligned.m16n8k8.row.col.f32.tf32.tf32.f32 "        \
                 "{%0,%1,%2,%3}, {%4,%5,%6,%7}, {%8,%9}, {%0,%1,%2,%3};"      \
                 : "+f"((c)[0]), "+f"((c)[1]), "+f"((c)[2]), "+f"((c)[3])     \
                 : "r"(a0), "r"(a1), "r"(a2), "r"(a3), "r"(b0), "r"(b1));

#define FMA8(ar, av, w0, w1)                 \
    ar[0] = fmaf(av, w0.x, ar[0]);           \
    ar[1] = fmaf(av, w0.y, ar[1]);           \
    ar[2] = fmaf(av, w0.z, ar[2]);           \
    ar[3] = fmaf(av, w0.w, ar[3]);           \
    ar[4] = fmaf(av, w1.x, ar[4]);           \
    ar[5] = fmaf(av, w1.y, ar[5]);           \
    ar[6] = fmaf(av, w1.z, ar[6]);           \
    ar[7] = fmaf(av, w1.w, ar[7]);

// ---------------------------------------------------------------------------
__global__ void zero_agg_kernel() {
    size_t i = (size_t)blockIdx.x * blockDim.x + threadIdx.x;
    size_t stride = (size_t)gridDim.x * blockDim.x;
    float4* p = reinterpret_cast<float4*>(g_agg);
    const size_t n4 = (size_t)NN * CH / 4;
    float4 z = make_float4(0.f, 0.f, 0.f, 0.f);
    for (; i < n4; i += stride) p[i] = z;
}

// ---------------------------------------------------------------------------
// 3xTF32 warp-MMA GEMM core: acc[128x128 tile] += As[128x132] @ Ws^T
// As row-major [m][k], Ws stored as [n][k] (stride 132). Warp w owns rows
// m0=w*16; acc[j*4+q] = D fragment for n-tile j.
// ---------------------------------------------------------------------------
__device__ __forceinline__ void gemm_tile(const float* __restrict__ As,
                                          const float* __restrict__ Ws,
                                          float* acc, int m0, int lane)
{
    const int g = lane >> 2, t = lane & 3;
    const float* arow0 = As + (m0 + g) * TS + t;
    const float* arow1 = As + (m0 + g + 8) * TS + t;
    #pragma unroll 1
    for (int k0 = 0; k0 < CH; k0 += 8) {
        uint32_t ah[4], al[4];
        split_tf32(arow0[k0],     ah[0], al[0]);
        split_tf32(arow1[k0],     ah[1], al[1]);
        split_tf32(arow0[k0 + 4], ah[2], al[2]);
        split_tf32(arow1[k0 + 4], ah[3], al[3]);
        #pragma unroll
        for (int j = 0; j < 16; j++) {
            const float* wr = Ws + (j * 8 + g) * TS + k0 + t;
            uint32_t bh0, bl0, bh1, bl1;
            split_tf32(wr[0], bh0, bl0);
            split_tf32(wr[4], bh1, bl1);
            float* c = acc + j * 4;
            MMA(c, ah[0], ah[1], ah[2], ah[3], bh0, bh1);
            MMA(c, al[0], al[1], al[2], al[3], bh0, bh1);
            MMA(c, ah[0], ah[1], ah[2], ah[3], bl0, bl1);
        }
    }
}

// ---------------------------------------------------------------------------
// h = features @ W_lin^T via 3xTF32 MMA.  WT[n][k] = W_lin[n*128+k] (direct).
// ---------------------------------------------------------------------------
__global__ __launch_bounds__(256, 1)
void node_linear_kernel(const float* __restrict__ feat, const float* __restrict__ W)
{
    extern __shared__ float sm[];
    float* As = sm;               // [128][132]
    float* Ws = sm + 128 * TS;    // [128][132]
    const int tid = threadIdx.x;
    const int lane = tid & 31;
    const int m0 = (tid >> 5) * 16;
    const int n0 = blockIdx.x * 128;

    for (int i = tid; i < CH * CH; i += 256) {
        int n = i >> 7, k = i & 127;
        Ws[n * TS + k] = W[i];
    }
    for (int i = tid; i < 128 * 32; i += 256) {
        int r = i >> 5, k4 = i & 31;
        int n = n0 + r;
        float4 v = make_float4(0.f, 0.f, 0.f, 0.f);
        if (n < NN) v = reinterpret_cast<const float4*>(feat)[(size_t)n * 32 + k4];
        *reinterpret_cast<float4*>(As + r * TS + k4 * 4) = v;
    }
    __syncthreads();

    float acc[64];
    #pragma unroll
    for (int i = 0; i < 64; i++) acc[i] = 0.f;
    gemm_tile(As, Ws, acc, m0, lane);
    __syncthreads();

    const int g = lane >> 2, t = lane & 3;
    #pragma unroll
    for (int j = 0; j < 16; j++) {
        int col = j * 8 + 2 * t;
        *reinterpret_cast<float2*>(As + (m0 + g) * TS + col)     = make_float2(acc[j*4+0], acc[j*4+1]);
        *reinterpret_cast<float2*>(As + (m0 + g + 8) * TS + col) = make_float2(acc[j*4+2], acc[j*4+3]);
    }
    __syncthreads();

    for (int i = tid; i < 128 * 32; i += 256) {
        int r = i >> 5, k4 = i & 31;
        int n = n0 + r;
        if (n < NN)
            reinterpret_cast<float4*>(g_h)[(size_t)n * 32 + k4] =
                *reinterpret_cast<const float4*>(As + r * TS + k4 * 4);
    }
}

// ---------------------------------------------------------------------------
// out = ssp(agg @ Wm1 + bm1) @ Wm2 + bm2 via 3xTF32 MMA.
// WT[n][k] = Wm[k*128+n] (transposed copy).
// ---------------------------------------------------------------------------
__global__ __launch_bounds__(256, 1)
void out_mlp_kernel(const float* __restrict__ Wm1, const float* __restrict__ bm1,
                    const float* __restrict__ Wm2, const float* __restrict__ bm2,
                    float* __restrict__ out)
{
    extern __shared__ float sm[];
    float* As = sm;               // [128][132]
    float* Ws = sm + 128 * TS;    // [128][132]
    float* bs = Ws + 128 * TS;    // [128]
    const int tid = threadIdx.x;
    const int lane = tid & 31;
    const int m0 = (tid >> 5) * 16;
    const int n0 = blockIdx.x * 128;
    const int g = lane >> 2, t = lane & 3;

    for (int i = tid; i < CH * CH; i += 256) {
        int k = i >> 7, n = i & 127;
        Ws[n * TS + k] = Wm1[i];
    }
    if (tid < CH) bs[tid] = bm1[tid];
    for (int i = tid; i < 128 * 32; i += 256) {
        int r = i >> 5, k4 = i & 31;
        int n = n0 + r;
        float4 v = make_float4(0.f, 0.f, 0.f, 0.f);
        if (n < NN) v = reinterpret_cast<const float4*>(g_agg)[(size_t)n * 32 + k4];
        *reinterpret_cast<float4*>(As + r * TS + k4 * 4) = v;
    }
    __syncthreads();

    float acc[64];
    #pragma unroll
    for (int i = 0; i < 64; i++) acc[i] = 0.f;
    gemm_tile(As, Ws, acc, m0, lane);
    __syncthreads();                      // all reads of As/Ws done

    #pragma unroll
    for (int j = 0; j < 16; j++) {
        int col = j * 8 + 2 * t;
        float b0 = bs[col], b1 = bs[col + 1];
        *reinterpret_cast<float2*>(As + (m0 + g) * TS + col) =
            make_float2(ssp(acc[j*4+0] + b0), ssp(acc[j*4+1] + b1));
        *reinterpret_cast<float2*>(As + (m0 + g + 8) * TS + col) =
            make_float2(ssp(acc[j*4+2] + b0), ssp(acc[j*4+3] + b1));
    }
    for (int i = tid; i < CH * CH; i += 256) {
        int k = i >> 7, n = i & 127;
        Ws[n * TS + k] = Wm2[i];
    }
    if (tid < CH) bs[tid] = bm2[tid];
    __syncthreads();

    #pragma unroll
    for (int i = 0; i < 64; i++) acc[i] = 0.f;
    gemm_tile(As, Ws, acc, m0, lane);
    __syncthreads();

    #pragma unroll
    for (int j = 0; j < 16; j++) {
        int col = j * 8 + 2 * t;
        float b0 = bs[col], b1 = bs[col + 1];
        *reinterpret_cast<float2*>(As + (m0 + g) * TS + col) =
            make_float2(acc[j*4+0] + b0, acc[j*4+1] + b1);
        *reinterpret_cast<float2*>(As + (m0 + g + 8) * TS + col) =
            make_float2(acc[j*4+2] + b0, acc[j*4+3] + b1);
    }
    __syncthreads();

    for (int i = tid; i < 128 * 32; i += 256) {
        int r = i >> 5, k4 = i & 31;
        int n = n0 + r;
        if (n < NN)
            reinterpret_cast<float4*>(out)[(size_t)n * 32 + k4] =
                *reinterpret_cast<const float4*>(As + r * TS + k4 * 4);
    }
}

// ---------------------------------------------------------------------------
// Build table: ef(r_i), r_i = i*5/NTAB  (proven R1 FFMA tile kernel)
// ---------------------------------------------------------------------------
__global__ __launch_bounds__(256, 1)
void table_kernel(const float* __restrict__ Wf1, const float* __restrict__ bf1,
                  const float* __restrict__ Wf2, const float* __restrict__ bf2)
{
    extern __shared__ float sm[];
    float* Wf1s  = sm;
    float* Wf2s  = Wf1s + FE * CH;
    float* bf1s  = Wf2s + CH * CH;
    float* bf2s  = bf1s + CH;
    float* basis = bf2s + CH;
    float* t1    = basis + 128 * 53;

    const int tid = threadIdx.x;
    const int e0 = blockIdx.x * 128;
    const float H = 5.0f / (float)NTAB;

    for (int i = tid; i < FE * CH; i += 256) Wf1s[i] = Wf1[i];
    for (int i = tid; i < CH * CH; i += 256) Wf2s[i] = Wf2[i];
    if (tid < CH) { bf1s[tid] = bf1[tid]; bf2s[tid] = bf2[tid]; }

    const float delta = 5.0f / 49.0f;
    const float coef  = 2401.0f / 50.0f;
    for (int i = tid; i < 128 * FE; i += 256) {
        int e = i / FE, f = i - e * FE;
        float r = (float)(e0 + e) * H;
        float d = r - delta * (float)f;
        basis[e * 53 + f] = __expf(-coef * d * d);
    }
    __syncthreads();

    const int ei = tid >> 4;
    const int c0 = (tid & 15) * 8;

    float acc[8][8];
    #pragma unroll
    for (int r = 0; r < 8; r++)
        #pragma unroll
        for (int j = 0; j < 8; j++) acc[r][j] = bf1s[c0 + j];

    #pragma unroll 2
    for (int f = 0; f < FE; f++) {
        float a[8];
        #pragma unroll
        for (int r = 0; r < 8; r++) a[r] = basis[(ei * 8 + r) * 53 + f];
        float4 w0 = *reinterpret_cast<const float4*>(Wf1s + f * CH + c0);
        float4 w1 = *reinterpret_cast<const float4*>(Wf1s + f * CH + c0 + 4);
        #pragma unroll
        for (int r = 0; r < 8; r++) { FMA8(acc[r], a[r], w0, w1); }
    }
    #pragma unroll
    for (int r = 0; r < 8; r++)
        #pragma unroll
        for (int j = 0; j < 8; j++)
            t1[(ei * 8 + r) * 130 + c0 + j] = ssp(acc[r][j]);
    __syncthreads();

    #pragma unroll
    for (int r = 0; r < 8; r++)
        #pragma unroll
        for (int j = 0; j < 8; j++) acc[r][j] = bf2s[c0 + j];

    #pragma unroll 2
    for (int k = 0; k < CH; k++) {
        float a[8];
        #pragma unroll
        for (int r = 0; r < 8; r++) a[r] = t1[(ei * 8 + r) * 130 + k];
        float4 w0 = *reinterpret_cast<const float4*>(Wf2s + k * CH + c0);
        float4 w1 = *reinterpret_cast<const float4*>(Wf2s + k * CH + c0 + 4);
        #pragma unroll
        for (int r = 0; r < 8; r++) { FMA8(acc[r], a[r], w0, w1); }
    }

    #pragma unroll
    for (int r = 0; r < 8; r++) {
        int row = e0 + ei * 8 + r;
        if (row <= NTAB) {
            float* dst = g_table + (size_t)row * CH + c0;
            *reinterpret_cast<float4*>(dst)     = make_float4(acc[r][0], acc[r][1], acc[r][2], acc[r][3]);
            *reinterpret_cast<float4*>(dst + 4) = make_float4(acc[r][4], acc[r][5], acc[r][6], acc[r][7]);
        }
    }
}

// ---------------------------------------------------------------------------
// Edge apply: 2 edges per warp-iteration (MLP=2), lerp table, mul h, scatter.
// ---------------------------------------------------------------------------
__global__ __launch_bounds__(256, 8)
void edge_apply_kernel(const float* __restrict__ dist,
                       const int* __restrict__ senders,
                       const int* __restrict__ receivers)
{
    const int lane = threadIdx.x & 31;
    const int warp = (blockIdx.x * blockDim.x + threadIdx.x) >> 5;
    const int nwarps = (gridDim.x * blockDim.x) >> 5;
    const float SCALE = (float)NTAB / 5.0f;

    for (int e = warp; e < NE; e += 2 * nwarps) {
        const int e2 = e + nwarps;
        const bool v2 = (e2 < NE);

        float r1 = __ldg(dist + e);
        int   s1 = __ldg(senders + e);
        int   c1 = __ldg(receivers + e);
        float r2 = 0.f; int s2 = 0, c2 = 0;
        if (v2) { r2 = __ldg(dist + e2); s2 = __ldg(senders + e2); c2 = __ldg(receivers + e2); }

        float u1 = r1 * SCALE;
        int   i1 = (int)u1;  i1 = i1 < 0 ? 0 : (i1 > NTAB - 1 ? NTAB - 1 : i1);
        float f1 = u1 - (float)i1;
        float u2 = r2 * SCALE;
        int   i2 = (int)u2;  i2 = i2 < 0 ? 0 : (i2 > NTAB - 1 ? NTAB - 1 : i2);
        float f2 = u2 - (float)i2;

        const float4* ta1 = reinterpret_cast<const float4*>(g_table + (size_t)i1 * CH) + lane;
        const float4* hp1 = reinterpret_cast<const float4*>(g_h + (size_t)s1 * CH) + lane;
        float4 a1 = ta1[0];
        float4 b1 = ta1[CH / 4];
        float4 h1 = hp1[0];

        float4 a2k, b2k, h2k;
        if (v2) {
            const float4* ta2 = reinterpret_cast<const float4*>(g_table + (size_t)i2 * CH) + lane;
            const float4* hp2 = reinterpret_cast<const float4*>(g_h + (size_t)s2 * CH) + lane;
            a2k = ta2[0];
            b2k = ta2[CH / 4];
            h2k = hp2[0];
        }

        float4 m1;
        m1.x = fmaf(f1, b1.x - a1.x, a1.x) * h1.x;
        m1.y = fmaf(f1, b1.y - a1.y, a1.y) * h1.y;
        m1.z = fmaf(f1, b1.z - a1.z, a1.z) * h1.z;
        m1.w = fmaf(f1, b1.w - a1.w, a1.w) * h1.w;
        red_add_v4(g_agg + (size_t)c1 * CH + lane * 4, m1);

        if (v2) {
            float4 m2;
            m2.x = fmaf(f2, b2k.x - a2k.x, a2k.x) * h2k.x;
            m2.y = fmaf(f2, b2k.y - a2k.y, a2k.y) * h2k.y;
            m2.z = fmaf(f2, b2k.z - a2k.z, a2k.z) * h2k.z;
            m2.w = fmaf(f2, b2k.w - a2k.w, a2k.w) * h2k.w;
            red_add_v4(g_agg + (size_t)c2 * CH + lane * 4, m2);
        }
    }
}

// ---------------------------------------------------------------------------
extern "C" void kernel_launch(void* const* d_in, const int* in_sizes, int n_in,
                              void* d_out, int out_size)
{
    const float* features = (const float*)d_in[0];
    const float* dist     = (const float*)d_in[1];
    const float* W_lin    = (const float*)d_in[2];
    const float* Wf1      = (const float*)d_in[3];
    const float* bf1      = (const float*)d_in[4];
    const float* Wf2      = (const float*)d_in[5];
    const float* bf2      = (const float*)d_in[6];
    const float* Wm1      = (const float*)d_in[7];
    const float* bm1      = (const float*)d_in[8];
    const float* Wm2      = (const float*)d_in[9];
    const float* bm2      = (const float*)d_in[10];
    const int*   senders   = (const int*)d_in[11];
    const int*   receivers = (const int*)d_in[12];
    float* out = (float*)d_out;

    const int smemA = (2 * 128 * TS) * 4;                                          // node mma
    const int smemT = (FE * CH + CH * CH + 2 * CH + 128 * 53 + 128 * 130) * 4;     // table
    const int smemC = (2 * 128 * TS + CH) * 4;                                     // out mma

    cudaFuncSetAttribute(node_linear_kernel, cudaFuncAttributeMaxDynamicSharedMemorySize, smemA);
    cudaFuncSetAttribute(table_kernel,       cudaFuncAttributeMaxDynamicSharedMemorySize, smemT);
    cudaFuncSetAttribute(out_mlp_kernel,     cudaFuncAttributeMaxDynamicSharedMemorySize, smemC);

    zero_agg_kernel<<<1024, 256>>>();
    table_kernel<<<(NTAB + 1 + 127) / 128, 256, smemT>>>(Wf1, bf1, Wf2, bf2);
    node_linear_kernel<<<(NN + 127) / 128, 256, smemA>>>(features, W_lin);
    edge_apply_kernel<<<2048, 256>>>(dist, senders, receivers);
    out_mlp_kernel<<<(NN + 127) / 128, 256, smemC>>>(Wm1, bm1, Wm2, bm2, out);
}

// round 6
// speedup vs baseline: 1.4004x; 1.4004x over previous
#include <cuda_runtime.h>
#include <math.h>
#include <stdint.h>

#define NN 50000
#define NE 1600000
#define CH 128
#define FE 50
#define TS 132
#define NTAB 16384

__device__ float g_h[(size_t)NN * CH];
__device__ float g_agg[(size_t)NN * CH];
__device__ float g_table[(size_t)(NTAB + 1) * CH];

__device__ __forceinline__ float ssp(float x) {
    return fmaxf(x, 0.0f) + log1pf(__expf(-fabsf(x))) - 0.69314718055994530942f;
}
__device__ __forceinline__ void red_add_v4(float* addr, float4 v) {
    asm volatile("red.global.add.v4.f32 [%0], {%1,%2,%3,%4};"
                 :: "l"(addr), "f"(v.x), "f"(v.y), "f"(v.z), "f"(v.w) : "memory");
}
__device__ __forceinline__ void split_tf32(float x, uint32_t& hi, uint32_t& lo) {
    asm("cvt.rna.tf32.f32 %0, %1;" : "=r"(hi) : "f"(x));
    float r = x - __uint_as_float(hi);
    asm("cvt.rna.tf32.f32 %0, %1;" : "=r"(lo) : "f"(r));
}
#define MMA(c, a0, a1, a2, a3, b0, b1)                                        \
    asm volatile("mma.sync.aligned.m16n8k8.row.col.f32.tf32.tf32.f32 "        \
                 "{%0,%1,%2,%3}, {%4,%5,%6,%7}, {%8,%9}, {%0,%1,%2,%3};"      \
                 : "+f"((c)[0]), "+f"((c)[1]), "+f"((c)[2]), "+f"((c)[3])     \
                 : "r"(a0), "r"(a1), "r"(a2), "r"(a3), "r"(b0), "r"(b1));

#define FMA8(ar, av, w0, w1)                 \
    ar[0] = fmaf(av, w0.x, ar[0]);           \
    ar[1] = fmaf(av, w0.y, ar[1]);           \
    ar[2] = fmaf(av, w0.z, ar[2]);           \
    ar[3] = fmaf(av, w0.w, ar[3]);           \
    ar[4] = fmaf(av, w1.x, ar[4]);           \
    ar[5] = fmaf(av, w1.y, ar[5]);           \
    ar[6] = fmaf(av, w1.z, ar[6]);           \
    ar[7] = fmaf(av, w1.w, ar[7]);

// ---------------------------------------------------------------------------
__global__ void zero_agg_kernel() {
    size_t i = (size_t)blockIdx.x * blockDim.x + threadIdx.x;
    size_t stride = (size_t)gridDim.x * blockDim.x;
    float4* p = reinterpret_cast<float4*>(g_agg);
    const size_t n4 = (size_t)NN * CH / 4;
    float4 z = make_float4(0.f, 0.f, 0.f, 0.f);
    for (; i < n4; i += stride) p[i] = z;
}

// ---------------------------------------------------------------------------
// Pre-split 3xTF32 warp-MMA GEMM core.
// As row-major fp32 [m][k] (split in-loop, 8 splits/k0);
// Wh/Wl pre-split tf32 hi/lo, layout [n][k], stride TS.
// Warp owns rows m0..m0+15; acc[j*4+q] = D fragment for n-tile j.
// ---------------------------------------------------------------------------
__device__ __forceinline__ void gemm_ps(const float* __restrict__ As,
                                        const uint32_t* __restrict__ Wh,
                                        const uint32_t* __restrict__ Wl,
                                        float* acc, int m0, int lane)
{
    const int g = lane >> 2, t = lane & 3;
    const float* arow0 = As + (m0 + g) * TS + t;
    const float* arow1 = As + (m0 + g + 8) * TS + t;
    #pragma unroll 1
    for (int k0 = 0; k0 < CH; k0 += 8) {
        uint32_t ah[4], al[4];
        split_tf32(arow0[k0],     ah[0], al[0]);
        split_tf32(arow1[k0],     ah[1], al[1]);
        split_tf32(arow0[k0 + 4], ah[2], al[2]);
        split_tf32(arow1[k0 + 4], ah[3], al[3]);
        #pragma unroll
        for (int j = 0; j < 16; j++) {
            const uint32_t* wh = Wh + (j * 8 + g) * TS + k0 + t;
            const uint32_t* wl = Wl + (j * 8 + g) * TS + k0 + t;
            uint32_t bh0 = wh[0], bh1 = wh[4];
            uint32_t bl0 = wl[0], bl1 = wl[4];
            float* c = acc + j * 4;
            MMA(c, ah[0], ah[1], ah[2], ah[3], bh0, bh1);
            MMA(c, al[0], al[1], al[2], al[3], bh0, bh1);
            MMA(c, ah[0], ah[1], ah[2], ah[3], bl0, bl1);
        }
    }
}

// ---------------------------------------------------------------------------
// h = features @ W_lin^T.  W stored [n][k] directly (W_lin rows are output ch).
// ---------------------------------------------------------------------------
__global__ __launch_bounds__(256, 1)
void node_linear_kernel(const float* __restrict__ feat, const float* __restrict__ W)
{
    extern __shared__ float sm[];
    float*    As = sm;                                   // [128][TS]
    uint32_t* Wh = reinterpret_cast<uint32_t*>(sm + 128 * TS);
    uint32_t* Wl = Wh + 128 * TS;
    const int tid = threadIdx.x;
    const int lane = tid & 31;
    const int m0 = (tid >> 5) * 16;
    const int n0 = blockIdx.x * 128;

    for (int i = tid; i < CH * CH; i += 256) {
        int n = i >> 7, k = i & 127;
        uint32_t hi, lo;
        split_tf32(W[i], hi, lo);
        Wh[n * TS + k] = hi;
        Wl[n * TS + k] = lo;
    }
    for (int i = tid; i < 128 * 32; i += 256) {
        int r = i >> 5, k4 = i & 31;
        int n = n0 + r;
        float4 v = make_float4(0.f, 0.f, 0.f, 0.f);
        if (n < NN) v = reinterpret_cast<const float4*>(feat)[(size_t)n * 32 + k4];
        *reinterpret_cast<float4*>(As + r * TS + k4 * 4) = v;
    }
    __syncthreads();

    float acc[64];
    #pragma unroll
    for (int i = 0; i < 64; i++) acc[i] = 0.f;
    gemm_ps(As, Wh, Wl, acc, m0, lane);
    __syncthreads();

    const int g = lane >> 2, t = lane & 3;
    #pragma unroll
    for (int j = 0; j < 16; j++) {
        int col = j * 8 + 2 * t;
        *reinterpret_cast<float2*>(As + (m0 + g) * TS + col)     = make_float2(acc[j*4+0], acc[j*4+1]);
        *reinterpret_cast<float2*>(As + (m0 + g + 8) * TS + col) = make_float2(acc[j*4+2], acc[j*4+3]);
    }
    __syncthreads();

    for (int i = tid; i < 128 * 32; i += 256) {
        int r = i >> 5, k4 = i & 31;
        int n = n0 + r;
        if (n < NN)
            reinterpret_cast<float4*>(g_h)[(size_t)n * 32 + k4] =
                *reinterpret_cast<const float4*>(As + r * TS + k4 * 4);
    }
}

// ---------------------------------------------------------------------------
// out = ssp(agg @ Wm1 + bm1) @ Wm2 + bm2.  Wm is [k][n] -> store [n][k].
// ---------------------------------------------------------------------------
__global__ __launch_bounds__(256, 1)
void out_mlp_kernel(const float* __restrict__ Wm1, const float* __restrict__ bm1,
                    const float* __restrict__ Wm2, const float* __restrict__ bm2,
                    float* __restrict__ out)
{
    extern __shared__ float sm[];
    float*    As = sm;                                   // [128][TS]
    uint32_t* Wh = reinterpret_cast<uint32_t*>(sm + 128 * TS);
    uint32_t* Wl = Wh + 128 * TS;
    float*    bs = reinterpret_cast<float*>(Wl + 128 * TS);   // [128]
    const int tid = threadIdx.x;
    const int lane = tid & 31;
    const int m0 = (tid >> 5) * 16;
    const int n0 = blockIdx.x * 128;
    const int g = lane >> 2, t = lane & 3;

    for (int i = tid; i < CH * CH; i += 256) {
        int k = i >> 7, n = i & 127;
        uint32_t hi, lo;
        split_tf32(Wm1[i], hi, lo);
        Wh[n * TS + k] = hi;
        Wl[n * TS + k] = lo;
    }
    if (tid < CH) bs[tid] = bm1[tid];
    for (int i = tid; i < 128 * 32; i += 256) {
        int r = i >> 5, k4 = i & 31;
        int n = n0 + r;
        float4 v = make_float4(0.f, 0.f, 0.f, 0.f);
        if (n < NN) v = reinterpret_cast<const float4*>(g_agg)[(size_t)n * 32 + k4];
        *reinterpret_cast<float4*>(As + r * TS + k4 * 4) = v;
    }
    __syncthreads();

    float acc[64];
    #pragma unroll
    for (int i = 0; i < 64; i++) acc[i] = 0.f;
    gemm_ps(As, Wh, Wl, acc, m0, lane);
    __syncthreads();                      // all reads of As/Wh/Wl done

    #pragma unroll
    for (int j = 0; j < 16; j++) {
        int col = j * 8 + 2 * t;
        float b0 = bs[col], b1 = bs[col + 1];
        *reinterpret_cast<float2*>(As + (m0 + g) * TS + col) =
            make_float2(ssp(acc[j*4+0] + b0), ssp(acc[j*4+1] + b1));
        *reinterpret_cast<float2*>(As + (m0 + g + 8) * TS + col) =
            make_float2(ssp(acc[j*4+2] + b0), ssp(acc[j*4+3] + b1));
    }
    for (int i = tid; i < CH * CH; i += 256) {
        int k = i >> 7, n = i & 127;
        uint32_t hi, lo;
        split_tf32(Wm2[i], hi, lo);
        Wh[n * TS + k] = hi;
        Wl[n * TS + k] = lo;
    }
    if (tid < CH) bs[tid] = bm2[tid];
    __syncthreads();

    #pragma unroll
    for (int i = 0; i < 64; i++) acc[i] = 0.f;
    gemm_ps(As, Wh, Wl, acc, m0, lane);
    __syncthreads();

    #pragma unroll
    for (int j = 0; j < 16; j++) {
        int col = j * 8 + 2 * t;
        float b0 = bs[col], b1 = bs[col + 1];
        *reinterpret_cast<float2*>(As + (m0 + g) * TS + col) =
            make_float2(acc[j*4+0] + b0, acc[j*4+1] + b1);
        *reinterpret_cast<float2*>(As + (m0 + g + 8) * TS + col) =
            make_float2(acc[j*4+2] + b0, acc[j*4+3] + b1);
    }
    __syncthreads();

    for (int i = tid; i < 128 * 32; i += 256) {
        int r = i >> 5, k4 = i & 31;
        int n = n0 + r;
        if (n < NN)
            reinterpret_cast<float4*>(out)[(size_t)n * 32 + k4] =
                *reinterpret_cast<const float4*>(As + r * TS + k4 * 4);
    }
}

// ---------------------------------------------------------------------------
// Build table: ef(r_i), r_i = i*5/NTAB  (proven R1 FFMA tile kernel)
// ---------------------------------------------------------------------------
__global__ __launch_bounds__(256, 1)
void table_kernel(const float* __restrict__ Wf1, const float* __restrict__ bf1,
                  const float* __restrict__ Wf2, const float* __restrict__ bf2)
{
    extern __shared__ float sm[];
    float* Wf1s  = sm;
    float* Wf2s  = Wf1s + FE * CH;
    float* bf1s  = Wf2s + CH * CH;
    float* bf2s  = bf1s + CH;
    float* basis = bf2s + CH;
    float* t1    = basis + 128 * 53;

    const int tid = threadIdx.x;
    const int e0 = blockIdx.x * 128;
    const float H = 5.0f / (float)NTAB;

    for (int i = tid; i < FE * CH; i += 256) Wf1s[i] = Wf1[i];
    for (int i = tid; i < CH * CH; i += 256) Wf2s[i] = Wf2[i];
    if (tid < CH) { bf1s[tid] = bf1[tid]; bf2s[tid] = bf2[tid]; }

    const float delta = 5.0f / 49.0f;
    const float coef  = 2401.0f / 50.0f;
    for (int i = tid; i < 128 * FE; i += 256) {
        int e = i / FE, f = i - e * FE;
        float r = (float)(e0 + e) * H;
        float d = r - delta * (float)f;
        basis[e * 53 + f] = __expf(-coef * d * d);
    }
    __syncthreads();

    const int ei = tid >> 4;
    const int c0 = (tid & 15) * 8;

    float acc[8][8];
    #pragma unroll
    for (int r = 0; r < 8; r++)
        #pragma unroll
        for (int j = 0; j < 8; j++) acc[r][j] = bf1s[c0 + j];

    #pragma unroll 2
    for (int f = 0; f < FE; f++) {
        float a[8];
        #pragma unroll
        for (int r = 0; r < 8; r++) a[r] = basis[(ei * 8 + r) * 53 + f];
        float4 w0 = *reinterpret_cast<const float4*>(Wf1s + f * CH + c0);
        float4 w1 = *reinterpret_cast<const float4*>(Wf1s + f * CH + c0 + 4);
        #pragma unroll
        for (int r = 0; r < 8; r++) { FMA8(acc[r], a[r], w0, w1); }
    }
    #pragma unroll
    for (int r = 0; r < 8; r++)
        #pragma unroll
        for (int j = 0; j < 8; j++)
            t1[(ei * 8 + r) * 130 + c0 + j] = ssp(acc[r][j]);
    __syncthreads();

    #pragma unroll
    for (int r = 0; r < 8; r++)
        #pragma unroll
        for (int j = 0; j < 8; j++) acc[r][j] = bf2s[c0 + j];

    #pragma unroll 2
    for (int k = 0; k < CH; k++) {
        float a[8];
        #pragma unroll
        for (int r = 0; r < 8; r++) a[r] = t1[(ei * 8 + r) * 130 + k];
        float4 w0 = *reinterpret_cast<const float4*>(Wf2s + k * CH + c0);
        float4 w1 = *reinterpret_cast<const float4*>(Wf2s + k * CH + c0 + 4);
        #pragma unroll
        for (int r = 0; r < 8; r++) { FMA8(acc[r], a[r], w0, w1); }
    }

    #pragma unroll
    for (int r = 0; r < 8; r++) {
        int row = e0 + ei * 8 + r;
        if (row <= NTAB) {
            float* dst = g_table + (size_t)row * CH + c0;
            *reinterpret_cast<float4*>(dst)     = make_float4(acc[r][0], acc[r][1], acc[r][2], acc[r][3]);
            *reinterpret_cast<float4*>(dst + 4) = make_float4(acc[r][4], acc[r][5], acc[r][6], acc[r][7]);
        }
    }
}

// ---------------------------------------------------------------------------
// Edge apply (exact R4 form — empirically fastest): one warp per edge,
// lerp table row pair, multiply gathered h, vector scatter-add.
// ---------------------------------------------------------------------------
__global__ __launch_bounds__(256, 8)
void edge_apply_kernel(const float* __restrict__ dist,
                       const int* __restrict__ senders,
                       const int* __restrict__ receivers)
{
    const int lane = threadIdx.x & 31;
    int warp = (blockIdx.x * blockDim.x + threadIdx.x) >> 5;
    const int nwarps = (gridDim.x * blockDim.x) >> 5;
    const float SCALE = (float)NTAB / 5.0f;

    for (int e = warp; e < NE; e += nwarps) {
        float r = __ldg(dist + e);
        int s  = __ldg(senders + e);
        int rc = __ldg(receivers + e);

        float u = r * SCALE;
        int i = (int)u;
        i = i < 0 ? 0 : (i > NTAB - 1 ? NTAB - 1 : i);
        float f = u - (float)i;

        const float4* ta = reinterpret_cast<const float4*>(g_table + (size_t)i * CH) + lane;
        float4 a = ta[0];
        float4 b = ta[CH / 4];
        const float4* hp = reinterpret_cast<const float4*>(g_h + (size_t)s * CH) + lane;
        float4 hv = hp[0];

        float4 m;
        m.x = fmaf(f, b.x - a.x, a.x) * hv.x;
        m.y = fmaf(f, b.y - a.y, a.y) * hv.y;
        m.z = fmaf(f, b.z - a.z, a.z) * hv.z;
        m.w = fmaf(f, b.w - a.w, a.w) * hv.w;

        red_add_v4(g_agg + (size_t)rc * CH + lane * 4, m);
    }
}

// ---------------------------------------------------------------------------
extern "C" void kernel_launch(void* const* d_in, const int* in_sizes, int n_in,
                              void* d_out, int out_size)
{
    const float* features = (const float*)d_in[0];
    const float* dist     = (const float*)d_in[1];
    const float* W_lin    = (const float*)d_in[2];
    const float* Wf1      = (const float*)d_in[3];
    const float* bf1      = (const float*)d_in[4];
    const float* Wf2      = (const float*)d_in[5];
    const float* bf2      = (const float*)d_in[6];
    const float* Wm1      = (const float*)d_in[7];
    const float* bm1      = (const float*)d_in[8];
    const float* Wm2      = (const float*)d_in[9];
    const float* bm2      = (const float*)d_in[10];
    const int*   senders   = (const int*)d_in[11];
    const int*   receivers = (const int*)d_in[12];
    float* out = (float*)d_out;

    const int smemA = (3 * 128 * TS) * 4;                                          // node mma (As+Wh+Wl)
    const int smemT = (FE * CH + CH * CH + 2 * CH + 128 * 53 + 128 * 130) * 4;     // table
    const int smemC = (3 * 128 * TS + CH) * 4;                                     // out mma (+bias)

    cudaFuncSetAttribute(node_linear_kernel, cudaFuncAttributeMaxDynamicSharedMemorySize, smemA);
    cudaFuncSetAttribute(table_kernel,       cudaFuncAttributeMaxDynamicSharedMemorySize, smemT);
    cudaFuncSetAttribute(out_mlp_kernel,     cudaFuncAttributeMaxDynamicSharedMemorySize, smemC);

    zero_agg_kernel<<<1024, 256>>>();
    table_kernel<<<(NTAB + 1 + 127) / 128, 256, smemT>>>(Wf1, bf1, Wf2, bf2);
    node_linear_kernel<<<(NN + 127) / 128, 256, smemA>>>(features, W_lin);
    edge_apply_kernel<<<2048, 256>>>(dist, senders, receivers);
    out_mlp_kernel<<<(NN + 127) / 128, 256, smemC>>>(Wm1, bm1, Wm2, bm2, out);
}

// round 7
// speedup vs baseline: 1.4129x; 1.0089x over previous
#include <cuda_runtime.h>
#include <cuda_fp16.h>
#include <math.h>
#include <stdint.h>

#define NN 50000
#define NE 1600000
#define CH 128
#define FE 50
#define TS 132
#define NTAB 16384

__device__ float g_h[(size_t)NN * CH];
__device__ float g_agg[(size_t)NN * CH];
__device__ float g_table[(size_t)(NTAB + 1) * CH];
__device__ __half2 g_tab2[(size_t)NTAB * CH];       // (v_i, v_{i+1}) per channel

__device__ __forceinline__ float ssp(float x) {
    return fmaxf(x, 0.0f) + log1pf(__expf(-fabsf(x))) - 0.69314718055994530942f;
}
__device__ __forceinline__ void red_add_v4(float* addr, float4 v) {
    asm volatile("red.global.add.v4.f32 [%0], {%1,%2,%3,%4};"
                 :: "l"(addr), "f"(v.x), "f"(v.y), "f"(v.z), "f"(v.w) : "memory");
}
__device__ __forceinline__ void split_tf32(float x, uint32_t& hi, uint32_t& lo) {
    asm("cvt.rna.tf32.f32 %0, %1;" : "=r"(hi) : "f"(x));
    float r = x - __uint_as_float(hi);
    asm("cvt.rna.tf32.f32 %0, %1;" : "=r"(lo) : "f"(r));
}
#define MMA(c, a0, a1, a2, a3, b0, b1)                                        \
    asm volatile("mma.sync.aligned.m16n8k8.row.col.f32.tf32.tf32.f32 "        \
                 "{%0,%1,%2,%3}, {%4,%5,%6,%7}, {%8,%9}, {%0,%1,%2,%3};"      \
                 : "+f"((c)[0]), "+f"((c)[1]), "+f"((c)[2]), "+f"((c)[3])     \
                 : "r"(a0), "r"(a1), "r"(a2), "r"(a3), "r"(b0), "r"(b1));

#define FMA8(ar, av, w0, w1)                 \
    ar[0] = fmaf(av, w0.x, ar[0]);           \
    ar[1] = fmaf(av, w0.y, ar[1]);           \
    ar[2] = fmaf(av, w0.z, ar[2]);           \
    ar[3] = fmaf(av, w0.w, ar[3]);           \
    ar[4] = fmaf(av, w1.x, ar[4]);           \
    ar[5] = fmaf(av, w1.y, ar[5]);           \
    ar[6] = fmaf(av, w1.z, ar[6]);           \
    ar[7] = fmaf(av, w1.w, ar[7]);

// ---------------------------------------------------------------------------
__global__ void zero_agg_kernel() {
    size_t i = (size_t)blockIdx.x * blockDim.x + threadIdx.x;
    size_t stride = (size_t)gridDim.x * blockDim.x;
    float4* p = reinterpret_cast<float4*>(g_agg);
    const size_t n4 = (size_t)NN * CH / 4;
    float4 z = make_float4(0.f, 0.f, 0.f, 0.f);
    for (; i < n4; i += stride) p[i] = z;
}

// Convert fp32 table -> interleaved fp16 endpoint table
__global__ void tab2_kernel() {
    int idx = blockIdx.x * blockDim.x + threadIdx.x;     // one (row, channel)
    if (idx < NTAB * CH) {
        int i = idx >> 7, c = idx & 127;
        float a = g_table[(size_t)i * CH + c];
        float b = g_table[(size_t)(i + 1) * CH + c];
        g_tab2[(size_t)i * CH + c] = __floats2half2_rn(a, b);
    }
}

// ---------------------------------------------------------------------------
// Pre-split 3xTF32 warp-MMA GEMM core.
// ---------------------------------------------------------------------------
__device__ __forceinline__ void gemm_ps(const float* __restrict__ As,
                                        const uint32_t* __restrict__ Wh,
                                        const uint32_t* __restrict__ Wl,
                                        float* acc, int m0, int lane)
{
    const int g = lane >> 2, t = lane & 3;
    const float* arow0 = As + (m0 + g) * TS + t;
    const float* arow1 = As + (m0 + g + 8) * TS + t;
    #pragma unroll 1
    for (int k0 = 0; k0 < CH; k0 += 8) {
        uint32_t ah[4], al[4];
        split_tf32(arow0[k0],     ah[0], al[0]);
        split_tf32(arow1[k0],     ah[1], al[1]);
        split_tf32(arow0[k0 + 4], ah[2], al[2]);
        split_tf32(arow1[k0 + 4], ah[3], al[3]);
        #pragma unroll
        for (int j = 0; j < 16; j++) {
            const uint32_t* wh = Wh + (j * 8 + g) * TS + k0 + t;
            const uint32_t* wl = Wl + (j * 8 + g) * TS + k0 + t;
            uint32_t bh0 = wh[0], bh1 = wh[4];
            uint32_t bl0 = wl[0], bl1 = wl[4];
            float* c = acc + j * 4;
            MMA(c, ah[0], ah[1], ah[2], ah[3], bh0, bh1);
            MMA(c, al[0], al[1], al[2], al[3], bh0, bh1);
            MMA(c, ah[0], ah[1], ah[2], ah[3], bl0, bl1);
        }
    }
}

// ---------------------------------------------------------------------------
// h = features @ W_lin^T
// ---------------------------------------------------------------------------
__global__ __launch_bounds__(256, 1)
void node_linear_kernel(const float* __restrict__ feat, const float* __restrict__ W)
{
    extern __shared__ float sm[];
    float*    As = sm;
    uint32_t* Wh = reinterpret_cast<uint32_t*>(sm + 128 * TS);
    uint32_t* Wl = Wh + 128 * TS;
    const int tid = threadIdx.x;
    const int lane = tid & 31;
    const int m0 = (tid >> 5) * 16;
    const int n0 = blockIdx.x * 128;

    for (int i = tid; i < CH * CH; i += 256) {
        int n = i >> 7, k = i & 127;
        uint32_t hi, lo;
        split_tf32(W[i], hi, lo);
        Wh[n * TS + k] = hi;
        Wl[n * TS + k] = lo;
    }
    for (int i = tid; i < 128 * 32; i += 256) {
        int r = i >> 5, k4 = i & 31;
        int n = n0 + r;
        float4 v = make_float4(0.f, 0.f, 0.f, 0.f);
        if (n < NN) v = reinterpret_cast<const float4*>(feat)[(size_t)n * 32 + k4];
        *reinterpret_cast<float4*>(As + r * TS + k4 * 4) = v;
    }
    __syncthreads();

    float acc[64];
    #pragma unroll
    for (int i = 0; i < 64; i++) acc[i] = 0.f;
    gemm_ps(As, Wh, Wl, acc, m0, lane);
    __syncthreads();

    const int g = lane >> 2, t = lane & 3;
    #pragma unroll
    for (int j = 0; j < 16; j++) {
        int col = j * 8 + 2 * t;
        *reinterpret_cast<float2*>(As + (m0 + g) * TS + col)     = make_float2(acc[j*4+0], acc[j*4+1]);
        *reinterpret_cast<float2*>(As + (m0 + g + 8) * TS + col) = make_float2(acc[j*4+2], acc[j*4+3]);
    }
    __syncthreads();

    for (int i = tid; i < 128 * 32; i += 256) {
        int r = i >> 5, k4 = i & 31;
        int n = n0 + r;
        if (n < NN)
            reinterpret_cast<float4*>(g_h)[(size_t)n * 32 + k4] =
                *reinterpret_cast<const float4*>(As + r * TS + k4 * 4);
    }
}

// ---------------------------------------------------------------------------
// out = ssp(agg @ Wm1 + bm1) @ Wm2 + bm2
// ---------------------------------------------------------------------------
__global__ __launch_bounds__(256, 1)
void out_mlp_kernel(const float* __restrict__ Wm1, const float* __restrict__ bm1,
                    const float* __restrict__ Wm2, const float* __restrict__ bm2,
                    float* __restrict__ out)
{
    extern __shared__ float sm[];
    float*    As = sm;
    uint32_t* Wh = reinterpret_cast<uint32_t*>(sm + 128 * TS);
    uint32_t* Wl = Wh + 128 * TS;
    float*    bs = reinterpret_cast<float*>(Wl + 128 * TS);
    const int tid = threadIdx.x;
    const int lane = tid & 31;
    const int m0 = (tid >> 5) * 16;
    const int n0 = blockIdx.x * 128;
    const int g = lane >> 2, t = lane & 3;

    for (int i = tid; i < CH * CH; i += 256) {
        int k = i >> 7, n = i & 127;
        uint32_t hi, lo;
        split_tf32(Wm1[i], hi, lo);
        Wh[n * TS + k] = hi;
        Wl[n * TS + k] = lo;
    }
    if (tid < CH) bs[tid] = bm1[tid];
    for (int i = tid; i < 128 * 32; i += 256) {
        int r = i >> 5, k4 = i & 31;
        int n = n0 + r;
        float4 v = make_float4(0.f, 0.f, 0.f, 0.f);
        if (n < NN) v = reinterpret_cast<const float4*>(g_agg)[(size_t)n * 32 + k4];
        *reinterpret_cast<float4*>(As + r * TS + k4 * 4) = v;
    }
    __syncthreads();

    float acc[64];
    #pragma unroll
    for (int i = 0; i < 64; i++) acc[i] = 0.f;
    gemm_ps(As, Wh, Wl, acc, m0, lane);
    __syncthreads();

    #pragma unroll
    for (int j = 0; j < 16; j++) {
        int col = j * 8 + 2 * t;
        float b0 = bs[col], b1 = bs[col + 1];
        *reinterpret_cast<float2*>(As + (m0 + g) * TS + col) =
            make_float2(ssp(acc[j*4+0] + b0), ssp(acc[j*4+1] + b1));
        *reinterpret_cast<float2*>(As + (m0 + g + 8) * TS + col) =
            make_float2(ssp(acc[j*4+2] + b0), ssp(acc[j*4+3] + b1));
    }
    for (int i = tid; i < CH * CH; i += 256) {
        int k = i >> 7, n = i & 127;
        uint32_t hi, lo;
        split_tf32(Wm2[i], hi, lo);
        Wh[n * TS + k] = hi;
        Wl[n * TS + k] = lo;
    }
    if (tid < CH) bs[tid] = bm2[tid];
    __syncthreads();

    #pragma unroll
    for (int i = 0; i < 64; i++) acc[i] = 0.f;
    gemm_ps(As, Wh, Wl, acc, m0, lane);
    __syncthreads();

    #pragma unroll
    for (int j = 0; j < 16; j++) {
        int col = j * 8 + 2 * t;
        float b0 = bs[col], b1 = bs[col + 1];
        *reinterpret_cast<float2*>(As + (m0 + g) * TS + col) =
            make_float2(acc[j*4+0] + b0, acc[j*4+1] + b1);
        *reinterpret_cast<float2*>(As + (m0 + g + 8) * TS + col) =
            make_float2(acc[j*4+2] + b0, acc[j*4+3] + b1);
    }
    __syncthreads();

    for (int i = tid; i < 128 * 32; i += 256) {
        int r = i >> 5, k4 = i & 31;
        int n = n0 + r;
        if (n < NN)
            reinterpret_cast<float4*>(out)[(size_t)n * 32 + k4] =
                *reinterpret_cast<const float4*>(As + r * TS + k4 * 4);
    }
}

// ---------------------------------------------------------------------------
// Build table: ef(r_i), r_i = i*5/NTAB
// ---------------------------------------------------------------------------
__global__ __launch_bounds__(256, 1)
void table_kernel(const float* __restrict__ Wf1, const float* __restrict__ bf1,
                  const float* __restrict__ Wf2, const float* __restrict__ bf2)
{
    extern __shared__ float sm[];
    float* Wf1s  = sm;
    float* Wf2s  = Wf1s + FE * CH;
    float* bf1s  = Wf2s + CH * CH;
    float* bf2s  = bf1s + CH;
    float* basis = bf2s + CH;
    float* t1    = basis + 128 * 53;

    const int tid = threadIdx.x;
    const int e0 = blockIdx.x * 128;
    const float H = 5.0f / (float)NTAB;

    for (int i = tid; i < FE * CH; i += 256) Wf1s[i] = Wf1[i];
    for (int i = tid; i < CH * CH; i += 256) Wf2s[i] = Wf2[i];
    if (tid < CH) { bf1s[tid] = bf1[tid]; bf2s[tid] = bf2[tid]; }

    const float delta = 5.0f / 49.0f;
    const float coef  = 2401.0f / 50.0f;
    for (int i = tid; i < 128 * FE; i += 256) {
        int e = i / FE, f = i - e * FE;
        float r = (float)(e0 + e) * H;
        float d = r - delta * (float)f;
        basis[e * 53 + f] = __expf(-coef * d * d);
    }
    __syncthreads();

    const int ei = tid >> 4;
    const int c0 = (tid & 15) * 8;

    float acc[8][8];
    #pragma unroll
    for (int r = 0; r < 8; r++)
        #pragma unroll
        for (int j = 0; j < 8; j++) acc[r][j] = bf1s[c0 + j];

    #pragma unroll 2
    for (int f = 0; f < FE; f++) {
        float a[8];
        #pragma unroll
        for (int r = 0; r < 8; r++) a[r] = basis[(ei * 8 + r) * 53 + f];
        float4 w0 = *reinterpret_cast<const float4*>(Wf1s + f * CH + c0);
        float4 w1 = *reinterpret_cast<const float4*>(Wf1s + f * CH + c0 + 4);
        #pragma unroll
        for (int r = 0; r < 8; r++) { FMA8(acc[r], a[r], w0, w1); }
    }
    #pragma unroll
    for (int r = 0; r < 8; r++)
        #pragma unroll
        for (int j = 0; j < 8; j++)
            t1[(ei * 8 + r) * 130 + c0 + j] = ssp(acc[r][j]);
    __syncthreads();

    #pragma unroll
    for (int r = 0; r < 8; r++)
        #pragma unroll
        for (int j = 0; j < 8; j++) acc[r][j] = bf2s[c0 + j];

    #pragma unroll 2
    for (int k = 0; k < CH; k++) {
        float a[8];
        #pragma unroll
        for (int r = 0; r < 8; r++) a[r] = t1[(ei * 8 + r) * 130 + k];
        float4 w0 = *reinterpret_cast<const float4*>(Wf2s + k * CH + c0);
        float4 w1 = *reinterpret_cast<const float4*>(Wf2s + k * CH + c0 + 4);
        #pragma unroll
        for (int r = 0; r < 8; r++) { FMA8(acc[r], a[r], w0, w1); }
    }

    #pragma unroll
    for (int r = 0; r < 8; r++) {
        int row = e0 + ei * 8 + r;
        if (row <= NTAB) {
            float* dst = g_table + (size_t)row * CH + c0;
            *reinterpret_cast<float4*>(dst)     = make_float4(acc[r][0], acc[r][1], acc[r][2], acc[r][3]);
            *reinterpret_cast<float4*>(dst + 4) = make_float4(acc[r][4], acc[r][5], acc[r][6], acc[r][7]);
        }
    }
}

// ---------------------------------------------------------------------------
// Edge apply: one warp per edge; fp16 interleaved endpoint table (one 512B
// row read gives both lerp endpoints), fp32 h gather, vector scatter-add.
// ---------------------------------------------------------------------------
__global__ __launch_bounds__(256, 8)
void edge_apply_kernel(const float* __restrict__ dist,
                       const int* __restrict__ senders,
                       const int* __restrict__ receivers)
{
    const int lane = threadIdx.x & 31;
    int warp = (blockIdx.x * blockDim.x + threadIdx.x) >> 5;
    const int nwarps = (gridDim.x * blockDim.x) >> 5;
    const float SCALE = (float)NTAB / 5.0f;

    for (int e = warp; e < NE; e += nwarps) {
        float r = __ldg(dist + e);
        int s  = __ldg(senders + e);
        int rc = __ldg(receivers + e);

        float u = r * SCALE;
        int i = (int)u;
        i = i < 0 ? 0 : (i > NTAB - 1 ? NTAB - 1 : i);
        float f = u - (float)i;

        uint4 tw = *reinterpret_cast<const uint4*>(
            reinterpret_cast<const __half2*>(g_tab2) + (size_t)i * CH + lane * 4);
        const float4* hp = reinterpret_cast<const float4*>(g_h + (size_t)s * CH) + lane;
        float4 hv = hp[0];

        float2 p0 = __half22float2(*reinterpret_cast<__half2*>(&tw.x));
        float2 p1 = __half22float2(*reinterpret_cast<__half2*>(&tw.y));
        float2 p2 = __half22float2(*reinterpret_cast<__half2*>(&tw.z));
        float2 p3 = __half22float2(*reinterpret_cast<__half2*>(&tw.w));

        float4 m;
        m.x = fmaf(f, p0.y - p0.x, p0.x) * hv.x;
        m.y = fmaf(f, p1.y - p1.x, p1.x) * hv.y;
        m.z = fmaf(f, p2.y - p2.x, p2.x) * hv.z;
        m.w = fmaf(f, p3.y - p3.x, p3.x) * hv.w;

        red_add_v4(g_agg + (size_t)rc * CH + lane * 4, m);
    }
}

// ---------------------------------------------------------------------------
extern "C" void kernel_launch(void* const* d_in, const int* in_sizes, int n_in,
                              void* d_out, int out_size)
{
    const float* features = (const float*)d_in[0];
    const float* dist     = (const float*)d_in[1];
    const float* W_lin    = (const float*)d_in[2];
    const float* Wf1      = (const float*)d_in[3];
    const float* bf1      = (const float*)d_in[4];
    const float* Wf2      = (const float*)d_in[5];
    const float* bf2      = (const float*)d_in[6];
    const float* Wm1      = (const float*)d_in[7];
    const float* bm1      = (const float*)d_in[8];
    const float* Wm2      = (const float*)d_in[9];
    const float* bm2      = (const float*)d_in[10];
    const int*   senders   = (const int*)d_in[11];
    const int*   receivers = (const int*)d_in[12];
    float* out = (float*)d_out;

    const int smemA = (3 * 128 * TS) * 4;
    const int smemT = (FE * CH + CH * CH + 2 * CH + 128 * 53 + 128 * 130) * 4;
    const int smemC = (3 * 128 * TS + CH) * 4;

    cudaFuncSetAttribute(node_linear_kernel, cudaFuncAttributeMaxDynamicSharedMemorySize, smemA);
    cudaFuncSetAttribute(table_kernel,       cudaFuncAttributeMaxDynamicSharedMemorySize, smemT);
    cudaFuncSetAttribute(out_mlp_kernel,     cudaFuncAttributeMaxDynamicSharedMemorySize, smemC);

    zero_agg_kernel<<<1024, 256>>>();
    table_kernel<<<(NTAB + 1 + 127) / 128, 256, smemT>>>(Wf1, bf1, Wf2, bf2);
    tab2_kernel<<<(NTAB * CH + 255) / 256, 256>>>();
    node_linear_kernel<<<(NN + 127) / 128, 256, smemA>>>(features, W_lin);
    edge_apply_kernel<<<2048, 256>>>(dist, senders, receivers);
    out_mlp_kernel<<<(NN + 127) / 128, 256, smemC>>>(Wm1, bm1, Wm2, bm2, out);
}

// round 8
// speedup vs baseline: 1.5563x; 1.1014x over previous
#include <cuda_runtime.h>
#include <cuda_fp16.h>
#include <math.h>
#include <stdint.h>

#define NN 50000
#define NE 1600000
#define CH 128
#define FE 50
#define TS 132
#define NTAB 16384
#define NCHUNK (NE / 32)

__device__ float g_h[(size_t)NN * CH];
__device__ float g_agg[(size_t)NN * CH];
__device__ float g_table[(size_t)(NTAB + 1) * CH];
__device__ __half2 g_tab2[(size_t)NTAB * CH];
// Fragment-packed tf32 split weights: [j(16)][kq(16)][lane(32)] float4 = (bh0,bh1,bl0,bl1)
__device__ float4 g_Wp0[8192];   // W_lin
__device__ float4 g_Wp1[8192];   // Wm1
__device__ float4 g_Wp2[8192];   // Wm2

__device__ __forceinline__ float ssp(float x) {
    return fmaxf(x, 0.0f) + log1pf(__expf(-fabsf(x))) - 0.69314718055994530942f;
}
__device__ __forceinline__ void red_add_v4(float* addr, float4 v) {
    asm volatile("red.global.add.v4.f32 [%0], {%1,%2,%3,%4};"
                 :: "l"(addr), "f"(v.x), "f"(v.y), "f"(v.z), "f"(v.w) : "memory");
}
__device__ __forceinline__ void split_tf32(float x, uint32_t& hi, uint32_t& lo) {
    asm("cvt.rna.tf32.f32 %0, %1;" : "=r"(hi) : "f"(x));
    float r = x - __uint_as_float(hi);
    asm("cvt.rna.tf32.f32 %0, %1;" : "=r"(lo) : "f"(r));
}
#define MMA(c, a0, a1, a2, a3, b0, b1)                                        \
    asm volatile("mma.sync.aligned.m16n8k8.row.col.f32.tf32.tf32.f32 "        \
                 "{%0,%1,%2,%3}, {%4,%5,%6,%7}, {%8,%9}, {%0,%1,%2,%3};"      \
                 : "+f"((c)[0]), "+f"((c)[1]), "+f"((c)[2]), "+f"((c)[3])     \
                 : "r"(a0), "r"(a1), "r"(a2), "r"(a3), "r"(b0), "r"(b1));

#define FMA8(ar, av, w0, w1)                 \
    ar[0] = fmaf(av, w0.x, ar[0]);           \
    ar[1] = fmaf(av, w0.y, ar[1]);           \
    ar[2] = fmaf(av, w0.z, ar[2]);           \
    ar[3] = fmaf(av, w0.w, ar[3]);           \
    ar[4] = fmaf(av, w1.x, ar[4]);           \
    ar[5] = fmaf(av, w1.y, ar[5]);           \
    ar[6] = fmaf(av, w1.z, ar[6]);           \
    ar[7] = fmaf(av, w1.w, ar[7]);

// ---------------------------------------------------------------------------
__global__ void zero_agg_kernel() {
    size_t i = (size_t)blockIdx.x * blockDim.x + threadIdx.x;
    size_t stride = (size_t)gridDim.x * blockDim.x;
    float4* p = reinterpret_cast<float4*>(g_agg);
    const size_t n4 = (size_t)NN * CH / 4;
    float4 z = make_float4(0.f, 0.f, 0.f, 0.f);
    for (; i < n4; i += stride) p[i] = z;
}

// fp32 table -> interleaved fp16 endpoint table
__global__ void tab2_kernel() {
    int idx = blockIdx.x * blockDim.x + threadIdx.x;
    if (idx < NTAB * CH) {
        int i = idx >> 7, c = idx & 127;
        float a = g_table[(size_t)i * CH + c];
        float b = g_table[(size_t)(i + 1) * CH + c];
        g_tab2[(size_t)i * CH + c] = __floats2half2_rn(a, b);
    }
}

// Pack the 3 node-GEMM weight matrices into MMA-fragment order, tf32 hi/lo.
__global__ void prep_pack_kernel(const float* __restrict__ W_lin,
                                 const float* __restrict__ Wm1,
                                 const float* __restrict__ Wm2)
{
    int idx = blockIdx.x * blockDim.x + threadIdx.x;
    if (idx >= 3 * 8192) return;
    int m = idx / 8192, r = idx - m * 8192;
    int lane = r & 31, jk = r >> 5;
    int kq = jk & 15, j = jk >> 4;
    int g = lane >> 2, t = lane & 3;
    int n = j * 8 + g, k0 = kq * 8;
    float b0, b1;
    if (m == 0) {                       // B[n][k] = W_lin[n][k]
        b0 = W_lin[n * CH + k0 + t];
        b1 = W_lin[n * CH + k0 + 4 + t];
    } else {                            // B[n][k] = Wm[k][n]
        const float* Wm = (m == 1) ? Wm1 : Wm2;
        b0 = Wm[(k0 + t) * CH + n];
        b1 = Wm[(k0 + 4 + t) * CH + n];
    }
    uint32_t h0, l0, h1, l1;
    split_tf32(b0, h0, l0);
    split_tf32(b1, h1, l1);
    float4 v = make_float4(__uint_as_float(h0), __uint_as_float(h1),
                           __uint_as_float(l0), __uint_as_float(l1));
    if (m == 0) g_Wp0[r] = v; else if (m == 1) g_Wp1[r] = v; else g_Wp2[r] = v;
}

// ---------------------------------------------------------------------------
// 3xTF32 warp-MMA GEMM, weights from fragment-packed global image (L1-hot).
// ---------------------------------------------------------------------------
__device__ __forceinline__ void gemm_pk(const float* __restrict__ As,
                                        const float4* __restrict__ P,
                                        float* acc, int m0, int lane)
{
    const int g = lane >> 2, t = lane & 3;
    const float* arow0 = As + (m0 + g) * TS + t;
    const float* arow1 = As + (m0 + g + 8) * TS + t;
    #pragma unroll 1
    for (int kq = 0; kq < 16; kq++) {
        const int k0 = kq * 8;
        uint32_t ah[4], al[4];
        split_tf32(arow0[k0],     ah[0], al[0]);
        split_tf32(arow1[k0],     ah[1], al[1]);
        split_tf32(arow0[k0 + 4], ah[2], al[2]);
        split_tf32(arow1[k0 + 4], ah[3], al[3]);
        #pragma unroll
        for (int j = 0; j < 16; j++) {
            float4 w = __ldg(P + ((j << 4) + kq) * 32 + lane);
            uint32_t bh0 = __float_as_uint(w.x), bh1 = __float_as_uint(w.y);
            uint32_t bl0 = __float_as_uint(w.z), bl1 = __float_as_uint(w.w);
            float* c = acc + j * 4;
            MMA(c, ah[0], ah[1], ah[2], ah[3], bh0, bh1);
            MMA(c, al[0], al[1], al[2], al[3], bh0, bh1);
            MMA(c, ah[0], ah[1], ah[2], ah[3], bl0, bl1);
        }
    }
}

// ---------------------------------------------------------------------------
// h = features @ W_lin^T
// ---------------------------------------------------------------------------
__global__ __launch_bounds__(256, 2)
void node_linear_kernel(const float* __restrict__ feat)
{
    extern __shared__ float sm[];
    float* As = sm;                       // [128][TS]
    const int tid = threadIdx.x;
    const int lane = tid & 31;
    const int m0 = (tid >> 5) * 16;
    const int n0 = blockIdx.x * 128;

    for (int i = tid; i < 128 * 32; i += 256) {
        int r = i >> 5, k4 = i & 31;
        int n = n0 + r;
        float4 v = make_float4(0.f, 0.f, 0.f, 0.f);
        if (n < NN) v = reinterpret_cast<const float4*>(feat)[(size_t)n * 32 + k4];
        *reinterpret_cast<float4*>(As + r * TS + k4 * 4) = v;
    }
    __syncthreads();

    float acc[64];
    #pragma unroll
    for (int i = 0; i < 64; i++) acc[i] = 0.f;
    gemm_pk(As, g_Wp0, acc, m0, lane);
    __syncthreads();

    const int g = lane >> 2, t = lane & 3;
    #pragma unroll
    for (int j = 0; j < 16; j++) {
        int col = j * 8 + 2 * t;
        *reinterpret_cast<float2*>(As + (m0 + g) * TS + col)     = make_float2(acc[j*4+0], acc[j*4+1]);
        *reinterpret_cast<float2*>(As + (m0 + g + 8) * TS + col) = make_float2(acc[j*4+2], acc[j*4+3]);
    }
    __syncthreads();

    for (int i = tid; i < 128 * 32; i += 256) {
        int r = i >> 5, k4 = i & 31;
        int n = n0 + r;
        if (n < NN)
            reinterpret_cast<float4*>(g_h)[(size_t)n * 32 + k4] =
                *reinterpret_cast<const float4*>(As + r * TS + k4 * 4);
    }
}

// ---------------------------------------------------------------------------
// out = ssp(agg @ Wm1 + bm1) @ Wm2 + bm2
// ---------------------------------------------------------------------------
__global__ __launch_bounds__(256, 2)
void out_mlp_kernel(const float* __restrict__ bm1, const float* __restrict__ bm2,
                    float* __restrict__ out)
{
    extern __shared__ float sm[];
    float* As = sm;                       // [128][TS]
    float* bs = sm + 128 * TS;            // [128]
    const int tid = threadIdx.x;
    const int lane = tid & 31;
    const int m0 = (tid >> 5) * 16;
    const int n0 = blockIdx.x * 128;
    const int g = lane >> 2, t = lane & 3;

    if (tid < CH) bs[tid] = bm1[tid];
    for (int i = tid; i < 128 * 32; i += 256) {
        int r = i >> 5, k4 = i & 31;
        int n = n0 + r;
        float4 v = make_float4(0.f, 0.f, 0.f, 0.f);
        if (n < NN) v = reinterpret_cast<const float4*>(g_agg)[(size_t)n * 32 + k4];
        *reinterpret_cast<float4*>(As + r * TS + k4 * 4) = v;
    }
    __syncthreads();

    float acc[64];
    #pragma unroll
    for (int i = 0; i < 64; i++) acc[i] = 0.f;
    gemm_pk(As, g_Wp1, acc, m0, lane);
    __syncthreads();

    #pragma unroll
    for (int j = 0; j < 16; j++) {
        int col = j * 8 + 2 * t;
        float b0 = bs[col], b1 = bs[col + 1];
        *reinterpret_cast<float2*>(As + (m0 + g) * TS + col) =
            make_float2(ssp(acc[j*4+0] + b0), ssp(acc[j*4+1] + b1));
        *reinterpret_cast<float2*>(As + (m0 + g + 8) * TS + col) =
            make_float2(ssp(acc[j*4+2] + b0), ssp(acc[j*4+3] + b1));
    }
    __syncthreads();
    if (tid < CH) bs[tid] = bm2[tid];
    __syncthreads();

    #pragma unroll
    for (int i = 0; i < 64; i++) acc[i] = 0.f;
    gemm_pk(As, g_Wp2, acc, m0, lane);
    __syncthreads();

    #pragma unroll
    for (int j = 0; j < 16; j++) {
        int col = j * 8 + 2 * t;
        float b0 = bs[col], b1 = bs[col + 1];
        *reinterpret_cast<float2*>(As + (m0 + g) * TS + col) =
            make_float2(acc[j*4+0] + b0, acc[j*4+1] + b1);
        *reinterpret_cast<float2*>(As + (m0 + g + 8) * TS + col) =
            make_float2(acc[j*4+2] + b0, acc[j*4+3] + b1);
    }
    __syncthreads();

    for (int i = tid; i < 128 * 32; i += 256) {
        int r = i >> 5, k4 = i & 31;
        int n = n0 + r;
        if (n < NN)
            reinterpret_cast<float4*>(out)[(size_t)n * 32 + k4] =
                *reinterpret_cast<const float4*>(As + r * TS + k4 * 4);
    }
}

// ---------------------------------------------------------------------------
// Build table: ef(r_i), r_i = i*5/NTAB  (proven FFMA tile kernel)
// ---------------------------------------------------------------------------
__global__ __launch_bounds__(256, 1)
void table_kernel(const float* __restrict__ Wf1, const float* __restrict__ bf1,
                  const float* __restrict__ Wf2, const float* __restrict__ bf2)
{
    extern __shared__ float sm[];
    float* Wf1s  = sm;
    float* Wf2s  = Wf1s + FE * CH;
    float* bf1s  = Wf2s + CH * CH;
    float* bf2s  = bf1s + CH;
    float* basis = bf2s + CH;
    float* t1    = basis + 128 * 53;

    const int tid = threadIdx.x;
    const int e0 = blockIdx.x * 128;
    const float H = 5.0f / (float)NTAB;

    for (int i = tid; i < FE * CH; i += 256) Wf1s[i] = Wf1[i];
    for (int i = tid; i < CH * CH; i += 256) Wf2s[i] = Wf2[i];
    if (tid < CH) { bf1s[tid] = bf1[tid]; bf2s[tid] = bf2[tid]; }

    const float delta = 5.0f / 49.0f;
    const float coef  = 2401.0f / 50.0f;
    for (int i = tid; i < 128 * FE; i += 256) {
        int e = i / FE, f = i - e * FE;
        float r = (float)(e0 + e) * H;
        float d = r - delta * (float)f;
        basis[e * 53 + f] = __expf(-coef * d * d);
    }
    __syncthreads();

    const int ei = tid >> 4;
    const int c0 = (tid & 15) * 8;

    float acc[8][8];
    #pragma unroll
    for (int r = 0; r < 8; r++)
        #pragma unroll
        for (int j = 0; j < 8; j++) acc[r][j] = bf1s[c0 + j];

    #pragma unroll 2
    for (int f = 0; f < FE; f++) {
        float a[8];
        #pragma unroll
        for (int r = 0; r < 8; r++) a[r] = basis[(ei * 8 + r) * 53 + f];
        float4 w0 = *reinterpret_cast<const float4*>(Wf1s + f * CH + c0);
        float4 w1 = *reinterpret_cast<const float4*>(Wf1s + f * CH + c0 + 4);
        #pragma unroll
        for (int r = 0; r < 8; r++) { FMA8(acc[r], a[r], w0, w1); }
    }
    #pragma unroll
    for (int r = 0; r < 8; r++)
        #pragma unroll
        for (int j = 0; j < 8; j++)
            t1[(ei * 8 + r) * 130 + c0 + j] = ssp(acc[r][j]);
    __syncthreads();

    #pragma unroll
    for (int r = 0; r < 8; r++)
        #pragma unroll
        for (int j = 0; j < 8; j++) acc[r][j] = bf2s[c0 + j];

    #pragma unroll 2
    for (int k = 0; k < CH; k++) {
        float a[8];
        #pragma unroll
        for (int r = 0; r < 8; r++) a[r] = t1[(ei * 8 + r) * 130 + k];
        float4 w0 = *reinterpret_cast<const float4*>(Wf2s + k * CH + c0);
        float4 w1 = *reinterpret_cast<const float4*>(Wf2s + k * CH + c0 + 4);
        #pragma unroll
        for (int r = 0; r < 8; r++) { FMA8(acc[r], a[r], w0, w1); }
    }

    #pragma unroll
    for (int r = 0; r < 8; r++) {
        int row = e0 + ei * 8 + r;
        if (row <= NTAB) {
            float* dst = g_table + (size_t)row * CH + c0;
            *reinterpret_cast<float4*>(dst)     = make_float4(acc[r][0], acc[r][1], acc[r][2], acc[r][3]);
            *reinterpret_cast<float4*>(dst + 4) = make_float4(acc[r][4], acc[r][5], acc[r][6], acc[r][7]);
        }
    }
}

// ---------------------------------------------------------------------------
// Edge apply: warp owns 32 consecutive edges. Coalesced metadata load once,
// then shfl-broadcast loop with double-buffered (table,h) prefetch.
// ---------------------------------------------------------------------------
__global__ __launch_bounds__(256, 8)
void edge_apply_kernel(const float* __restrict__ dist,
                       const int* __restrict__ senders,
                       const int* __restrict__ receivers)
{
    const int lane = threadIdx.x & 31;
    const int warp = (blockIdx.x * blockDim.x + threadIdx.x) >> 5;
    const int nwarps = (gridDim.x * blockDim.x) >> 5;
    const float SCALE = (float)NTAB / 5.0f;
    const unsigned FULL = 0xFFFFFFFFu;

    for (int c = warp; c < NCHUNK; c += nwarps) {
        const int e0 = c << 5;
        float dl = __ldg(dist + e0 + lane);
        int   sl = __ldg(senders + e0 + lane);
        int   rl = __ldg(receivers + e0 + lane);

        // prefetch k = 0
        float d0 = __shfl_sync(FULL, dl, 0);
        int   s0 = __shfl_sync(FULL, sl, 0);
        float u = d0 * SCALE;
        int   i = (int)u;  i = i < 0 ? 0 : (i > NTAB - 1 ? NTAB - 1 : i);
        float fcur = u - (float)i;
        uint4 tw = __ldg(reinterpret_cast<const uint4*>(
            reinterpret_cast<const __half2*>(g_tab2) + (size_t)i * CH) + lane);
        float4 hv = __ldg(reinterpret_cast<const float4*>(g_h + (size_t)s0 * CH) + lane);

        #pragma unroll 1
        for (int k = 0; k < 32; k++) {
            // prefetch k+1 (k=31 redundantly reloads k=31; harmless L1 hit)
            const int kn = (k + 1 < 32) ? k + 1 : 31;
            float dn = __shfl_sync(FULL, dl, kn);
            int   sn = __shfl_sync(FULL, sl, kn);
            float un = dn * SCALE;
            int   in = (int)un;  in = in < 0 ? 0 : (in > NTAB - 1 ? NTAB - 1 : in);
            float fn = un - (float)in;
            uint4 twn = __ldg(reinterpret_cast<const uint4*>(
                reinterpret_cast<const __half2*>(g_tab2) + (size_t)in * CH) + lane);
            float4 hvn = __ldg(reinterpret_cast<const float4*>(g_h + (size_t)sn * CH) + lane);

            int rk = __shfl_sync(FULL, rl, k);
            float2 p0 = __half22float2(*reinterpret_cast<__half2*>(&tw.x));
            float2 p1 = __half22float2(*reinterpret_cast<__half2*>(&tw.y));
            float2 p2 = __half22float2(*reinterpret_cast<__half2*>(&tw.z));
            float2 p3 = __half22float2(*reinterpret_cast<__half2*>(&tw.w));
            float4 m;
            m.x = fmaf(fcur, p0.y - p0.x, p0.x) * hv.x;
            m.y = fmaf(fcur, p1.y - p1.x, p1.x) * hv.y;
            m.z = fmaf(fcur, p2.y - p2.x, p2.x) * hv.z;
            m.w = fmaf(fcur, p3.y - p3.x, p3.x) * hv.w;
            red_add_v4(g_agg + (size_t)rk * CH + lane * 4, m);

            tw = twn; hv = hvn; fcur = fn;
        }
    }
}

// ---------------------------------------------------------------------------
extern "C" void kernel_launch(void* const* d_in, const int* in_sizes, int n_in,
                              void* d_out, int out_size)
{
    const float* features = (const float*)d_in[0];
    const float* dist     = (const float*)d_in[1];
    const float* W_lin    = (const float*)d_in[2];
    const float* Wf1      = (const float*)d_in[3];
    const float* bf1      = (const float*)d_in[4];
    const float* Wf2      = (const float*)d_in[5];
    const float* bf2      = (const float*)d_in[6];
    const float* Wm1      = (const float*)d_in[7];
    const float* bm1      = (const float*)d_in[8];
    const float* Wm2      = (const float*)d_in[9];
    const float* bm2      = (const float*)d_in[10];
    const int*   senders   = (const int*)d_in[11];
    const int*   receivers = (const int*)d_in[12];
    float* out = (float*)d_out;

    const int smemA = 128 * TS * 4;                                            // 67584
    const int smemT = (FE * CH + CH * CH + 2 * CH + 128 * 53 + 128 * 130) * 4;
    const int smemC = (128 * TS + CH) * 4;                                     // 68096

    cudaFuncSetAttribute(node_linear_kernel, cudaFuncAttributeMaxDynamicSharedMemorySize, smemA);
    cudaFuncSetAttribute(table_kernel,       cudaFuncAttributeMaxDynamicSharedMemorySize, smemT);
    cudaFuncSetAttribute(out_mlp_kernel,     cudaFuncAttributeMaxDynamicSharedMemorySize, smemC);

    zero_agg_kernel<<<1024, 256>>>();
    table_kernel<<<(NTAB + 1 + 127) / 128, 256, smemT>>>(Wf1, bf1, Wf2, bf2);
    tab2_kernel<<<(NTAB * CH + 255) / 256, 256>>>();
    prep_pack_kernel<<<96, 256>>>(W_lin, Wm1, Wm2);
    node_linear_kernel<<<(NN + 127) / 128, 256, smemA>>>(features);
    edge_apply_kernel<<<2048, 256>>>(dist, senders, receivers);
    out_mlp_kernel<<<(NN + 127) / 128, 256, smemC>>>(bm1, bm2, out);
}

// round 9
// speedup vs baseline: 1.6237x; 1.0433x over previous
#include <cuda_runtime.h>
#include <cuda_fp16.h>
#include <math.h>
#include <stdint.h>

#define NN 50000
#define NE 1600000
#define CH 128
#define FE 50
#define TS 132
#define NTAB 16384
#define NCHUNK (NE / 32)

__device__ __half2 g_h2[(size_t)NN * 64];            // h in fp16, packed pairs
__device__ float g_agg[(size_t)NN * CH];
__device__ float g_table[(size_t)(NTAB + 1) * CH];
__device__ __half2 g_tab2[(size_t)NTAB * CH];
// Fragment-packed tf32 split weights: [j(16)][kq(16)][lane(32)] float4 = (bh0,bh1,bl0,bl1)
__device__ float4 g_Wp0[8192];   // W_lin
__device__ float4 g_Wp1[8192];   // Wm1
__device__ float4 g_Wp2[8192];   // Wm2

__device__ __forceinline__ float ssp(float x) {
    return fmaxf(x, 0.0f) + log1pf(__expf(-fabsf(x))) - 0.69314718055994530942f;
}
__device__ __forceinline__ void red_add_v4(float* addr, float4 v) {
    asm volatile("red.global.add.v4.f32 [%0], {%1,%2,%3,%4};"
                 :: "l"(addr), "f"(v.x), "f"(v.y), "f"(v.z), "f"(v.w) : "memory");
}
__device__ __forceinline__ void split_tf32(float x, uint32_t& hi, uint32_t& lo) {
    asm("cvt.rna.tf32.f32 %0, %1;" : "=r"(hi) : "f"(x));
    float r = x - __uint_as_float(hi);
    asm("cvt.rna.tf32.f32 %0, %1;" : "=r"(lo) : "f"(r));
}
#define MMA(c, a0, a1, a2, a3, b0, b1)                                        \
    asm volatile("mma.sync.aligned.m16n8k8.row.col.f32.tf32.tf32.f32 "        \
                 "{%0,%1,%2,%3}, {%4,%5,%6,%7}, {%8,%9}, {%0,%1,%2,%3};"      \
                 : "+f"((c)[0]), "+f"((c)[1]), "+f"((c)[2]), "+f"((c)[3])     \
                 : "r"(a0), "r"(a1), "r"(a2), "r"(a3), "r"(b0), "r"(b1));

#define FMA8(ar, av, w0, w1)                 \
    ar[0] = fmaf(av, w0.x, ar[0]);           \
    ar[1] = fmaf(av, w0.y, ar[1]);           \
    ar[2] = fmaf(av, w0.z, ar[2]);           \
    ar[3] = fmaf(av, w0.w, ar[3]);           \
    ar[4] = fmaf(av, w1.x, ar[4]);           \
    ar[5] = fmaf(av, w1.y, ar[5]);           \
    ar[6] = fmaf(av, w1.z, ar[6]);           \
    ar[7] = fmaf(av, w1.w, ar[7]);

// ---------------------------------------------------------------------------
__global__ void zero_agg_kernel() {
    size_t i = (size_t)blockIdx.x * blockDim.x + threadIdx.x;
    size_t stride = (size_t)gridDim.x * blockDim.x;
    float4* p = reinterpret_cast<float4*>(g_agg);
    const size_t n4 = (size_t)NN * CH / 4;
    float4 z = make_float4(0.f, 0.f, 0.f, 0.f);
    for (; i < n4; i += stride) p[i] = z;
}

__global__ void tab2_kernel() {
    int idx = blockIdx.x * blockDim.x + threadIdx.x;
    if (idx < NTAB * CH) {
        int i = idx >> 7, c = idx & 127;
        float a = g_table[(size_t)i * CH + c];
        float b = g_table[(size_t)(i + 1) * CH + c];
        g_tab2[(size_t)i * CH + c] = __floats2half2_rn(a, b);
    }
}

__global__ void prep_pack_kernel(const float* __restrict__ W_lin,
                                 const float* __restrict__ Wm1,
                                 const float* __restrict__ Wm2)
{
    int idx = blockIdx.x * blockDim.x + threadIdx.x;
    if (idx >= 3 * 8192) return;
    int m = idx / 8192, r = idx - m * 8192;
    int lane = r & 31, jk = r >> 5;
    int kq = jk & 15, j = jk >> 4;
    int g = lane >> 2, t = lane & 3;
    int n = j * 8 + g, k0 = kq * 8;
    float b0, b1;
    if (m == 0) {
        b0 = W_lin[n * CH + k0 + t];
        b1 = W_lin[n * CH + k0 + 4 + t];
    } else {
        const float* Wm = (m == 1) ? Wm1 : Wm2;
        b0 = Wm[(k0 + t) * CH + n];
        b1 = Wm[(k0 + 4 + t) * CH + n];
    }
    uint32_t h0, l0, h1, l1;
    split_tf32(b0, h0, l0);
    split_tf32(b1, h1, l1);
    float4 v = make_float4(__uint_as_float(h0), __uint_as_float(h1),
                           __uint_as_float(l0), __uint_as_float(l1));
    if (m == 0) g_Wp0[r] = v; else if (m == 1) g_Wp1[r] = v; else g_Wp2[r] = v;
}

// ---------------------------------------------------------------------------
// 3xTF32 warp-MMA GEMM, weights from fragment-packed global image (L1-hot).
// ---------------------------------------------------------------------------
__device__ __forceinline__ void gemm_pk(const float* __restrict__ As,
                                        const float4* __restrict__ P,
                                        float* acc, int m0, int lane)
{
    const int g = lane >> 2, t = lane & 3;
    const float* arow0 = As + (m0 + g) * TS + t;
    const float* arow1 = As + (m0 + g + 8) * TS + t;
    #pragma unroll 1
    for (int kq = 0; kq < 16; kq++) {
        const int k0 = kq * 8;
        uint32_t ah[4], al[4];
        split_tf32(arow0[k0],     ah[0], al[0]);
        split_tf32(arow1[k0],     ah[1], al[1]);
        split_tf32(arow0[k0 + 4], ah[2], al[2]);
        split_tf32(arow1[k0 + 4], ah[3], al[3]);
        #pragma unroll
        for (int j = 0; j < 16; j++) {
            float4 w = __ldg(P + ((j << 4) + kq) * 32 + lane);
            uint32_t bh0 = __float_as_uint(w.x), bh1 = __float_as_uint(w.y);
            uint32_t bl0 = __float_as_uint(w.z), bl1 = __float_as_uint(w.w);
            float* c = acc + j * 4;
            MMA(c, ah[0], ah[1], ah[2], ah[3], bh0, bh1);
            MMA(c, al[0], al[1], al[2], al[3], bh0, bh1);
            MMA(c, ah[0], ah[1], ah[2], ah[3], bl0, bl1);
        }
    }
}

// ---------------------------------------------------------------------------
// h = features @ W_lin^T, emitted directly as fp16 pairs into g_h2.
// ---------------------------------------------------------------------------
__global__ __launch_bounds__(256, 2)
void node_linear_kernel(const float* __restrict__ feat)
{
    extern __shared__ float sm[];
    float* As = sm;                       // [128][TS]
    const int tid = threadIdx.x;
    const int lane = tid & 31;
    const int m0 = (tid >> 5) * 16;
    const int n0 = blockIdx.x * 128;

    for (int i = tid; i < 128 * 32; i += 256) {
        int r = i >> 5, k4 = i & 31;
        int n = n0 + r;
        float4 v = make_float4(0.f, 0.f, 0.f, 0.f);
        if (n < NN) v = reinterpret_cast<const float4*>(feat)[(size_t)n * 32 + k4];
        *reinterpret_cast<float4*>(As + r * TS + k4 * 4) = v;
    }
    __syncthreads();

    float acc[64];
    #pragma unroll
    for (int i = 0; i < 64; i++) acc[i] = 0.f;
    gemm_pk(As, g_Wp0, acc, m0, lane);
    __syncthreads();

    const int g = lane >> 2, t = lane & 3;
    #pragma unroll
    for (int j = 0; j < 16; j++) {
        int col = j * 8 + 2 * t;
        *reinterpret_cast<float2*>(As + (m0 + g) * TS + col)     = make_float2(acc[j*4+0], acc[j*4+1]);
        *reinterpret_cast<float2*>(As + (m0 + g + 8) * TS + col) = make_float2(acc[j*4+2], acc[j*4+3]);
    }
    __syncthreads();

    // convert row-major fp32 tile -> fp16 pairs, coalesced uint4 stores
    for (int i = tid; i < 128 * 16; i += 256) {
        int r = i >> 4, q = i & 15;       // q: group of 8 channels
        int n = n0 + r;
        if (n < NN) {
            const float* src = As + r * TS + q * 8;
            __half2 h0 = __floats2half2_rn(src[0], src[1]);
            __half2 h1 = __floats2half2_rn(src[2], src[3]);
            __half2 h2 = __floats2half2_rn(src[4], src[5]);
            __half2 h3 = __floats2half2_rn(src[6], src[7]);
            uint4 pk = make_uint4(*(uint32_t*)&h0, *(uint32_t*)&h1,
                                  *(uint32_t*)&h2, *(uint32_t*)&h3);
            reinterpret_cast<uint4*>(g_h2)[(size_t)n * 16 + q] = pk;
        }
    }
}

// ---------------------------------------------------------------------------
// out = ssp(agg @ Wm1 + bm1) @ Wm2 + bm2
// ---------------------------------------------------------------------------
__global__ __launch_bounds__(256, 2)
void out_mlp_kernel(const float* __restrict__ bm1, const float* __restrict__ bm2,
                    float* __restrict__ out)
{
    extern __shared__ float sm[];
    float* As = sm;                       // [128][TS]
    float* bs = sm + 128 * TS;            // [128]
    const int tid = threadIdx.x;
    const int lane = tid & 31;
    const int m0 = (tid >> 5) * 16;
    const int n0 = blockIdx.x * 128;
    const int g = lane >> 2, t = lane & 3;

    if (tid < CH) bs[tid] = bm1[tid];
    for (int i = tid; i < 128 * 32; i += 256) {
        int r = i >> 5, k4 = i & 31;
        int n = n0 + r;
        float4 v = make_float4(0.f, 0.f, 0.f, 0.f);
        if (n < NN) v = reinterpret_cast<const float4*>(g_agg)[(size_t)n * 32 + k4];
        *reinterpret_cast<float4*>(As + r * TS + k4 * 4) = v;
    }
    __syncthreads();

    float acc[64];
    #pragma unroll
    for (int i = 0; i < 64; i++) acc[i] = 0.f;
    gemm_pk(As, g_Wp1, acc, m0, lane);
    __syncthreads();

    #pragma unroll
    for (int j = 0; j < 16; j++) {
        int col = j * 8 + 2 * t;
        float b0 = bs[col], b1 = bs[col + 1];
        *reinterpret_cast<float2*>(As + (m0 + g) * TS + col) =
            make_float2(ssp(acc[j*4+0] + b0), ssp(acc[j*4+1] + b1));
        *reinterpret_cast<float2*>(As + (m0 + g + 8) * TS + col) =
            make_float2(ssp(acc[j*4+2] + b0), ssp(acc[j*4+3] + b1));
    }
    __syncthreads();
    if (tid < CH) bs[tid] = bm2[tid];
    __syncthreads();

    #pragma unroll
    for (int i = 0; i < 64; i++) acc[i] = 0.f;
    gemm_pk(As, g_Wp2, acc, m0, lane);
    __syncthreads();

    #pragma unroll
    for (int j = 0; j < 16; j++) {
        int col = j * 8 + 2 * t;
        float b0 = bs[col], b1 = bs[col + 1];
        *reinterpret_cast<float2*>(As + (m0 + g) * TS + col) =
            make_float2(acc[j*4+0] + b0, acc[j*4+1] + b1);
        *reinterpret_cast<float2*>(As + (m0 + g + 8) * TS + col) =
            make_float2(acc[j*4+2] + b0, acc[j*4+3] + b1);
    }
    __syncthreads();

    for (int i = tid; i < 128 * 32; i += 256) {
        int r = i >> 5, k4 = i & 31;
        int n = n0 + r;
        if (n < NN)
            reinterpret_cast<float4*>(out)[(size_t)n * 32 + k4] =
                *reinterpret_cast<const float4*>(As + r * TS + k4 * 4);
    }
}

// ---------------------------------------------------------------------------
// Build table: ef(r_i), r_i = i*5/NTAB  (proven FFMA tile kernel)
// ---------------------------------------------------------------------------
__global__ __launch_bounds__(256, 1)
void table_kernel(const float* __restrict__ Wf1, const float* __restrict__ bf1,
                  const float* __restrict__ Wf2, const float* __restrict__ bf2)
{
    extern __shared__ float sm[];
    float* Wf1s  = sm;
    float* Wf2s  = Wf1s + FE * CH;
    float* bf1s  = Wf2s + CH * CH;
    float* bf2s  = bf1s + CH;
    float* basis = bf2s + CH;
    float* t1    = basis + 128 * 53;

    const int tid = threadIdx.x;
    const int e0 = blockIdx.x * 128;
    const float H = 5.0f / (float)NTAB;

    for (int i = tid; i < FE * CH; i += 256) Wf1s[i] = Wf1[i];
    for (int i = tid; i < CH * CH; i += 256) Wf2s[i] = Wf2[i];
    if (tid < CH) { bf1s[tid] = bf1[tid]; bf2s[tid] = bf2[tid]; }

    const float delta = 5.0f / 49.0f;
    const float coef  = 2401.0f / 50.0f;
    for (int i = tid; i < 128 * FE; i += 256) {
        int e = i / FE, f = i - e * FE;
        float r = (float)(e0 + e) * H;
        float d = r - delta * (float)f;
        basis[e * 53 + f] = __expf(-coef * d * d);
    }
    __syncthreads();

    const int ei = tid >> 4;
    const int c0 = (tid & 15) * 8;

    float acc[8][8];
    #pragma unroll
    for (int r = 0; r < 8; r++)
        #pragma unroll
        for (int j = 0; j < 8; j++) acc[r][j] = bf1s[c0 + j];

    #pragma unroll 2
    for (int f = 0; f < FE; f++) {
        float a[8];
        #pragma unroll
        for (int r = 0; r < 8; r++) a[r] = basis[(ei * 8 + r) * 53 + f];
        float4 w0 = *reinterpret_cast<const float4*>(Wf1s + f * CH + c0);
        float4 w1 = *reinterpret_cast<const float4*>(Wf1s + f * CH + c0 + 4);
        #pragma unroll
        for (int r = 0; r < 8; r++) { FMA8(acc[r], a[r], w0, w1); }
    }
    #pragma unroll
    for (int r = 0; r < 8; r++)
        #pragma unroll
        for (int j = 0; j < 8; j++)
            t1[(ei * 8 + r) * 130 + c0 + j] = ssp(acc[r][j]);
    __syncthreads();

    #pragma unroll
    for (int r = 0; r < 8; r++)
        #pragma unroll
        for (int j = 0; j < 8; j++) acc[r][j] = bf2s[c0 + j];

    #pragma unroll 2
    for (int k = 0; k < CH; k++) {
        float a[8];
        #pragma unroll
        for (int r = 0; r < 8; r++) a[r] = t1[(ei * 8 + r) * 130 + k];
        float4 w0 = *reinterpret_cast<const float4*>(Wf2s + k * CH + c0);
        float4 w1 = *reinterpret_cast<const float4*>(Wf2s + k * CH + c0 + 4);
        #pragma unroll
        for (int r = 0; r < 8; r++) { FMA8(acc[r], a[r], w0, w1); }
    }

    #pragma unroll
    for (int r = 0; r < 8; r++) {
        int row = e0 + ei * 8 + r;
        if (row <= NTAB) {
            float* dst = g_table + (size_t)row * CH + c0;
            *reinterpret_cast<float4*>(dst)     = make_float4(acc[r][0], acc[r][1], acc[r][2], acc[r][3]);
            *reinterpret_cast<float4*>(dst + 4) = make_float4(acc[r][4], acc[r][5], acc[r][6], acc[r][7]);
        }
    }
}

// ---------------------------------------------------------------------------
// Edge apply: warp owns 32 consecutive edges; fp16 endpoint table + fp16 h.
// ---------------------------------------------------------------------------
__global__ __launch_bounds__(256, 8)
void edge_apply_kernel(const float* __restrict__ dist,
                       const int* __restrict__ senders,
                       const int* __restrict__ receivers)
{
    const int lane = threadIdx.x & 31;
    const int warp = (blockIdx.x * blockDim.x + threadIdx.x) >> 5;
    const int nwarps = (gridDim.x * blockDim.x) >> 5;
    const float SCALE = (float)NTAB / 5.0f;
    const unsigned FULL = 0xFFFFFFFFu;

    for (int c = warp; c < NCHUNK; c += nwarps) {
        const int e0 = c << 5;
        float dl = __ldg(dist + e0 + lane);
        int   sl = __ldg(senders + e0 + lane);
        int   rl = __ldg(receivers + e0 + lane);

        float d0 = __shfl_sync(FULL, dl, 0);
        int   s0 = __shfl_sync(FULL, sl, 0);
        float u = d0 * SCALE;
        int   i = (int)u;  i = i < 0 ? 0 : (i > NTAB - 1 ? NTAB - 1 : i);
        float fcur = u - (float)i;
        uint4 tw = __ldg(reinterpret_cast<const uint4*>(
            reinterpret_cast<const __half2*>(g_tab2) + (size_t)i * CH) + lane);
        uint2 hw = __ldg(reinterpret_cast<const uint2*>(g_h2 + (size_t)s0 * 64) + lane);

        #pragma unroll 1
        for (int k = 0; k < 32; k++) {
            const int kn = (k + 1 < 32) ? k + 1 : 31;
            float dn = __shfl_sync(FULL, dl, kn);
            int   sn = __shfl_sync(FULL, sl, kn);
            float un = dn * SCALE;
            int   in = (int)un;  in = in < 0 ? 0 : (in > NTAB - 1 ? NTAB - 1 : in);
            float fn = un - (float)in;
            uint4 twn = __ldg(reinterpret_cast<const uint4*>(
                reinterpret_cast<const __half2*>(g_tab2) + (size_t)in * CH) + lane);
            uint2 hwn = __ldg(reinterpret_cast<const uint2*>(g_h2 + (size_t)sn * 64) + lane);

            int rk = __shfl_sync(FULL, rl, k);
            float2 p0 = __half22float2(*reinterpret_cast<__half2*>(&tw.x));
            float2 p1 = __half22float2(*reinterpret_cast<__half2*>(&tw.y));
            float2 p2 = __half22float2(*reinterpret_cast<__half2*>(&tw.z));
            float2 p3 = __half22float2(*reinterpret_cast<__half2*>(&tw.w));
            float2 h01 = __half22float2(*reinterpret_cast<__half2*>(&hw.x));
            float2 h23 = __half22float2(*reinterpret_cast<__half2*>(&hw.y));
            float4 m;
            m.x = fmaf(fcur, p0.y - p0.x, p0.x) * h01.x;
            m.y = fmaf(fcur, p1.y - p1.x, p1.x) * h01.y;
            m.z = fmaf(fcur, p2.y - p2.x, p2.x) * h23.x;
            m.w = fmaf(fcur, p3.y - p3.x, p3.x) * h23.y;
            red_add_v4(g_agg + (size_t)rk * CH + lane * 4, m);

            tw = twn; hw = hwn; fcur = fn;
        }
    }
}

// ---------------------------------------------------------------------------
extern "C" void kernel_launch(void* const* d_in, const int* in_sizes, int n_in,
                              void* d_out, int out_size)
{
    const float* features = (const float*)d_in[0];
    const float* dist     = (const float*)d_in[1];
    const float* W_lin    = (const float*)d_in[2];
    const float* Wf1      = (const float*)d_in[3];
    const float* bf1      = (const float*)d_in[4];
    const float* Wf2      = (const float*)d_in[5];
    const float* bf2      = (const float*)d_in[6];
    const float* Wm1      = (const float*)d_in[7];
    const float* bm1      = (const float*)d_in[8];
    const float* Wm2      = (const float*)d_in[9];
    const float* bm2      = (const float*)d_in[10];
    const int*   senders   = (const int*)d_in[11];
    const int*   receivers = (const int*)d_in[12];
    float* out = (float*)d_out;

    const int smemA = 128 * TS * 4;
    const int smemT = (FE * CH + CH * CH + 2 * CH + 128 * 53 + 128 * 130) * 4;
    const int smemC = (128 * TS + CH) * 4;

    cudaFuncSetAttribute(node_linear_kernel, cudaFuncAttributeMaxDynamicSharedMemorySize, smemA);
    cudaFuncSetAttribute(table_kernel,       cudaFuncAttributeMaxDynamicSharedMemorySize, smemT);
    cudaFuncSetAttribute(out_mlp_kernel,     cudaFuncAttributeMaxDynamicSharedMemorySize, smemC);

    zero_agg_kernel<<<1024, 256>>>();
    table_kernel<<<(NTAB + 1 + 127) / 128, 256, smemT>>>(Wf1, bf1, Wf2, bf2);
    tab2_kernel<<<(NTAB * CH + 255) / 256, 256>>>();
    prep_pack_kernel<<<96, 256>>>(W_lin, Wm1, Wm2);
    node_linear_kernel<<<(NN + 127) / 128, 256, smemA>>>(features);
    edge_apply_kernel<<<2048, 256>>>(dist, senders, receivers);
    out_mlp_kernel<<<(NN + 127) / 128, 256, smemC>>>(bm1, bm2, out);
}